// round 9
// baseline (speedup 1.0000x reference)
#include <cuda_runtime.h>
#include <math.h>

#define BZ   4
#define QL   512
#define CL   1536
#define KVL  2048
#define E    1024
#define NH   16
#define HD   64
#define MROWS (BZ*QL)   // 2048

#define OUT_K ((size_t)MROWS*E)                       // 2097152
#define OUT_V (OUT_K + (size_t)BZ*KVL*E)              // 10485760

#define PO_ROWS (BZ*NH*QL)    // 32768
#define N_ITEMS 1024
#define ATTN_BLOCKS 444

// ---------------- scratch (tf32 stored as u32) -------------------------------
__device__ unsigned g_xt [MROWS*E];       // X  tf32
__device__ unsigned g_wqt[E*E];           // Wq tf32 [n][k]
__device__ unsigned g_wkt[E*E];
__device__ unsigned g_wvt[E*E];
__device__ unsigned g_wot[E*E];
__device__ unsigned g_q  [MROWS*E];       // Q proj, tf32, pre-scaled by 1/8
__device__ unsigned g_ctx[MROWS*E];       // attention ctx, tf32
__device__ unsigned g_kt [(size_t)BZ*KVL*E];  // full K (cache+new), tf32
__device__ unsigned g_vt [(size_t)BZ*KVL*E];  // full V, tf32

// split-KV partials
__device__ float g_po[(size_t)2*PO_ROWS*HD];  // unnormalized partial O
__device__ float g_pm[2*PO_ROWS];             // row max
__device__ float g_pl[2*PO_ROWS];             // row sum
__device__ unsigned g_work;                   // atomic work counter

// ---------------- helpers ----------------------------------------------------
__device__ __forceinline__ unsigned f2tf(float f) {
    unsigned u;
    asm("cvt.rna.tf32.f32 %0, %1;" : "=r"(u) : "f"(f));
    return u;
}

__device__ __forceinline__ void mma8(float* c,
                                     unsigned a0, unsigned a1, unsigned a2, unsigned a3,
                                     unsigned b0, unsigned b1)
{
    asm volatile(
        "mma.sync.aligned.m16n8k8.row.col.f32.tf32.tf32.f32 "
        "{%0,%1,%2,%3}, {%4,%5,%6,%7}, {%8,%9}, {%0,%1,%2,%3};\n"
        : "+f"(c[0]), "+f"(c[1]), "+f"(c[2]), "+f"(c[3])
        : "r"(a0), "r"(a1), "r"(a2), "r"(a3), "r"(b0), "r"(b1));
}

#define CP16(dst, src) \
    asm volatile("cp.async.cg.shared.global [%0], [%1], 16;\n" \
                 :: "r"(dst), "l"(src))
#define CPCOMMIT() asm volatile("cp.async.commit_group;\n" ::: "memory")
#define CPWAIT(n)  asm volatile("cp.async.wait_group %0;\n" :: "n"(n) : "memory")

// ---------------- init work counter ------------------------------------------
__global__ void init_work() { g_work = 0; }

// ---------------- convert inputs to tf32 -------------------------------------
__global__ void convert_tf32(const float4* __restrict__ X,
                             const float4* __restrict__ Wq,
                             const float4* __restrict__ Wk,
                             const float4* __restrict__ Wv,
                             const float4* __restrict__ Wo)
{
    int i = blockIdx.x*256 + threadIdx.x;
    const float4* src; uint4* dst; int off;
    if (i < 524288)       { src = X;  dst = (uint4*)g_xt;  off = i; }
    else if (i < 786432)  { src = Wq; dst = (uint4*)g_wqt; off = i - 524288; }
    else if (i < 1048576) { src = Wk; dst = (uint4*)g_wkt; off = i - 786432; }
    else if (i < 1310720) { src = Wv; dst = (uint4*)g_wvt; off = i - 1048576; }
    else                  { src = Wo; dst = (uint4*)g_wot; off = i - 1310720; }
    float4 v = src[off];
    uint4 u;
    u.x = f2tf(v.x); u.y = f2tf(v.y); u.z = f2tf(v.z); u.w = f2tf(v.w);
    dst[off] = u;
}

// ---------------- cache copy: f32 to dout + tf32 to g_kt/g_vt ----------------
__global__ void copy_cache(const float4* __restrict__ kc,
                           const float4* __restrict__ vc,
                           float* __restrict__ dout)
{
    const int per_b = CL*E/4;
    int idx = blockIdx.x*blockDim.x + threadIdx.x;
    if (idx >= BZ*per_b) return;
    int b = idx / per_b, rem = idx - b*per_b;
    size_t d = (size_t)b*(KVL*E/4) + rem;
    float4 k4 = kc[idx], v4 = vc[idx];
    ((float4*)(dout + OUT_K))[d] = k4;
    ((float4*)(dout + OUT_V))[d] = v4;
    uint4 u;
    u.x=f2tf(k4.x); u.y=f2tf(k4.y); u.z=f2tf(k4.z); u.w=f2tf(k4.w);
    ((uint4*)g_kt)[d] = u;
    u.x=f2tf(v4.x); u.y=f2tf(v4.y); u.z=f2tf(v4.z); u.w=f2tf(v4.w);
    ((uint4*)g_vt)[d] = u;
}

// ---------------- tf32 GEMM core (cp.async, 2-stage) -------------------------
#define GST 20

__device__ __forceinline__
void gemm_core(const unsigned* __restrict__ AGLOB,
               const unsigned* __restrict__ BGLOB,
               int bm, int nrow0, float acc[4][4][4])
{
    __shared__ __align__(16) unsigned sAB[4*128*GST];
    unsigned* Asm[2] = { sAB,             sAB + 128*GST   };
    unsigned* Bsm[2] = { sAB + 2*128*GST, sAB + 3*128*GST };
    unsigned aAddr[2], bAddr[2];
    aAddr[0] = (unsigned)__cvta_generic_to_shared(Asm[0]);
    aAddr[1] = (unsigned)__cvta_generic_to_shared(Asm[1]);
    bAddr[0] = (unsigned)__cvta_generic_to_shared(Bsm[0]);
    bAddr[1] = (unsigned)__cvta_generic_to_shared(Bsm[1]);

    int tid = threadIdx.x;
    int warp = tid >> 5, lane = tid & 31, g = lane >> 2, tig = lane & 3;
    int wm = (warp >> 2)*64, wn = (warp & 3)*32;
    int r0c = tid >> 2, c0c = (tid & 3)*4;
    int r1c = r0c + 64;

    auto issue = [&](int st, int k0) {
        CP16(aAddr[st] + (unsigned)((r0c*GST + c0c)*4),
             AGLOB + (size_t)(bm + r0c)*E + k0 + c0c);
        CP16(aAddr[st] + (unsigned)((r1c*GST + c0c)*4),
             AGLOB + (size_t)(bm + r1c)*E + k0 + c0c);
        CP16(bAddr[st] + (unsigned)((r0c*GST + c0c)*4),
             BGLOB + (size_t)(nrow0 + r0c)*E + k0 + c0c);
        CP16(bAddr[st] + (unsigned)((r1c*GST + c0c)*4),
             BGLOB + (size_t)(nrow0 + r1c)*E + k0 + c0c);
    };

    #pragma unroll
    for (int mt = 0; mt < 4; mt++)
        #pragma unroll
        for (int nt = 0; nt < 4; nt++)
            #pragma unroll
            for (int i = 0; i < 4; i++) acc[mt][nt][i] = 0.f;

    issue(0, 0);  CPCOMMIT();
    issue(1, 16); CPCOMMIT();

    for (int kt = 0; kt < 64; kt++) {
        int cur = kt & 1;
        if (kt < 63) { CPWAIT(1); } else { CPWAIT(0); }
        __syncthreads();
        #pragma unroll
        for (int kh = 0; kh < 2; kh++) {
            int kb = kh*8;
            unsigned af[4][4], bf[4][2];
            #pragma unroll
            for (int mt = 0; mt < 4; mt++) {
                int r = wm + mt*16;
                af[mt][0] = Asm[cur][(r+g  )*GST + kb + tig];
                af[mt][1] = Asm[cur][(r+g+8)*GST + kb + tig];
                af[mt][2] = Asm[cur][(r+g  )*GST + kb + tig + 4];
                af[mt][3] = Asm[cur][(r+g+8)*GST + kb + tig + 4];
            }
            #pragma unroll
            for (int nt = 0; nt < 4; nt++) {
                int cidx = wn + nt*8 + g;
                bf[nt][0] = Bsm[cur][cidx*GST + kb + tig];
                bf[nt][1] = Bsm[cur][cidx*GST + kb + tig + 4];
            }
            #pragma unroll
            for (int mt = 0; mt < 4; mt++)
                #pragma unroll
                for (int nt = 0; nt < 4; nt++)
                    mma8(acc[mt][nt], af[mt][0], af[mt][1], af[mt][2],
                         af[mt][3], bf[nt][0], bf[nt][1]);
        }
        __syncthreads();
        if (kt + 2 < 64) { issue(cur, (kt+2)*16); CPCOMMIT(); }
    }
}

// ---------------- QKV projection ---------------------------------------------
__global__ __launch_bounds__(256, 2)
void gemm_qkv(const float* __restrict__ bq, const float* __restrict__ bk,
              const float* __restrict__ bv, float* __restrict__ dout)
{
    int bn = blockIdx.x*128, bm = blockIdx.y*128;
    int seg = bn >> 10;            // 0=Q 1=K 2=V
    int nrow0 = bn & (E-1);
    const unsigned* Bglob = (seg == 0) ? g_wqt : (seg == 1) ? g_wkt : g_wvt;
    const float*    bias  = (seg == 0) ? bq   : (seg == 1) ? bk    : bv;

    float acc[4][4][4];
    gemm_core(g_xt, Bglob, bm, nrow0, acc);

    int tid = threadIdx.x;
    int warp = tid >> 5, lane = tid & 31, g = lane >> 2, tig = lane & 3;
    int wm = (warp >> 2)*64, wn = (warp & 3)*32;

    #pragma unroll
    for (int mt = 0; mt < 4; mt++) {
        int m = bm + wm + mt*16 + g;
        #pragma unroll
        for (int nt = 0; nt < 4; nt++) {
            int nl = nrow0 + wn + nt*8 + 2*tig;
            float b0 = bias[nl], b1 = bias[nl+1];
            float v0 = acc[mt][nt][0] + b0, v1 = acc[mt][nt][1] + b1;
            float v2 = acc[mt][nt][2] + b0, v3 = acc[mt][nt][3] + b1;
            if (seg == 0) {
                uint2 u0; u0.x = f2tf(v0*0.125f); u0.y = f2tf(v1*0.125f);
                uint2 u1; u1.x = f2tf(v2*0.125f); u1.y = f2tf(v3*0.125f);
                *(uint2*)&g_q[(size_t)m*E + nl]     = u0;
                *(uint2*)&g_q[(size_t)(m+8)*E + nl] = u1;
            } else {
                float* fbase = dout + (seg == 1 ? OUT_K : OUT_V);
                unsigned* tbase = (seg == 1) ? g_kt : g_vt;
                int ba = m >> 9,      t0 = m & 511;
                int bb = (m+8) >> 9,  t1 = (m+8) & 511;
                size_t ra = ((size_t)(ba*KVL) + CL + t0)*E + nl;
                size_t rb = ((size_t)(bb*KVL) + CL + t1)*E + nl;
                *(float2*)&fbase[ra] = make_float2(v0, v1);
                *(float2*)&fbase[rb] = make_float2(v2, v3);
                uint2 u0; u0.x = f2tf(v0); u0.y = f2tf(v1);
                uint2 u1; u1.x = f2tf(v2); u1.y = f2tf(v3);
                *(uint2*)&tbase[ra] = u0;
                *(uint2*)&tbase[rb] = u1;
            }
        }
    }
}

// ---------------- output projection ------------------------------------------
__global__ __launch_bounds__(256, 2)
void gemm_out(const float* __restrict__ bo, float* __restrict__ dout)
{
    int bn = blockIdx.x*128, bm = blockIdx.y*128;

    float acc[4][4][4];
    gemm_core(g_ctx, g_wot, bm, bn, acc);

    int tid = threadIdx.x;
    int warp = tid >> 5, lane = tid & 31, g = lane >> 2, tig = lane & 3;
    int wm = (warp >> 2)*64, wn = (warp & 3)*32;

    #pragma unroll
    for (int mt = 0; mt < 4; mt++) {
        int m = bm + wm + mt*16 + g;
        #pragma unroll
        for (int nt = 0; nt < 4; nt++) {
            int n = bn + wn + nt*8 + 2*tig;
            float b0 = bo[n], b1 = bo[n+1];
            *(float2*)&dout[(size_t)m*E + n] =
                make_float2(acc[mt][nt][0] + b0, acc[mt][nt][1] + b1);
            *(float2*)&dout[(size_t)(m+8)*E + n] =
                make_float2(acc[mt][nt][2] + b0, acc[mt][nt][3] + b1);
        }
    }
}

// ---------------- persistent split-KV flash attention ------------------------
// 444 blocks x 128 thr. Items: (qt desc, chunk, b, h) -> 1024 items, each a
// KV-chunk of ~12-16 tiles with its own online softmax; partials merged by
// combine_attn. Chunk 0 cols <= 1024 < CL -> no causal test needed there.
#define SWK(r,d) ((d) ^ ((((unsigned)(r))&7u)<<2))
#define SWV(r,d) ((d) ^ ((((unsigned)(r))&3u)<<3))

__global__ __launch_bounds__(128)
void attn(const float* __restrict__ amask)
{
    __shared__ __align__(16) unsigned sK[2][64*64];
    __shared__ __align__(16) unsigned sV[64*64];

    int tid  = threadIdx.x;
    int warp = tid >> 5, lane = tid & 31, g = lane >> 2, tig = lane & 3;
    int m0 = warp*16;

    unsigned kAddr[2], vAddr;
    kAddr[0] = (unsigned)__cvta_generic_to_shared(sK[0]);
    kAddr[1] = (unsigned)__cvta_generic_to_shared(sK[1]);
    vAddr    = (unsigned)__cvta_generic_to_shared(sV);

    for (;;) {
        __syncthreads();                       // prior item's smem reads done
        if (tid == 0)
            ((int*)sK)[0] = (int)atomicAdd(&g_work, 1u);
        __syncthreads();
        int item = ((int*)sK)[0];
        __syncthreads();                       // all read before smem reuse
        if (item >= N_ITEMS) break;

        // decode: qt descending (heavy first), chunk 0 (larger) first
        int qt    = 7 - (item >> 7);
        int r_    = item & 127;
        int chunk = r_ >> 6;
        int bh    = r_ & 63;
        int b     = bh >> 4, h = bh & 15;

        int nkt  = 25 + qt;
        int half = nkt >> 1;
        int t0   = chunk ? half : 0;
        int ntiles = chunk ? (nkt - half) : half;

        const unsigned* kg = g_kt + ((size_t)b*KVL)*E + h*HD;
        const unsigned* vg = g_vt + ((size_t)b*KVL)*E + h*HD;

        auto issueK = [&](int tile, int st) {
            const unsigned* src = kg + (size_t)tile*64*E;
            #pragma unroll
            for (int i = 0; i < 8; i++) {
                int c = tid + i*128;
                int row = c >> 4, c4 = (c & 15)*4;
                CP16(kAddr[st] + (unsigned)((row*64 + SWK(row, c4))*4),
                     src + (size_t)row*E + c4);
            }
        };
        auto issueV = [&](int tile) {
            const unsigned* src = vg + (size_t)tile*64*E;
            #pragma unroll
            for (int i = 0; i < 8; i++) {
                int c = tid + i*128;
                int row = c >> 4, c4 = (c & 15)*4;
                CP16(vAddr + (unsigned)((row*64 + SWV(row, c4))*4),
                     src + (size_t)row*E + c4);
            }
        };

        // Q fragments
        unsigned qf[8][4];
        {
            const unsigned* qb = g_q + ((size_t)(b*QL + qt*64))*E + h*HD;
            #pragma unroll
            for (int kc = 0; kc < 8; kc++) {
                int kb = kc*8;
                qf[kc][0] = __ldg(qb + (size_t)(m0+g  )*E + kb + tig);
                qf[kc][1] = __ldg(qb + (size_t)(m0+g+8)*E + kb + tig);
                qf[kc][2] = __ldg(qb + (size_t)(m0+g  )*E + kb + tig + 4);
                qf[kc][3] = __ldg(qb + (size_t)(m0+g+8)*E + kb + tig + 4);
            }
        }

        float O[8][4];
        #pragma unroll
        for (int nt = 0; nt < 8; nt++)
            #pragma unroll
            for (int i = 0; i < 4; i++) O[nt][i] = 0.f;
        float mi0 = -1e30f, mi1 = -1e30f, li0 = 0.f, li1 = 0.f;

        issueK(t0, 0); CPCOMMIT();

        for (int it = 0; it < ntiles; it++) {
            int kt  = t0 + it;
            int cur = it & 1;
            if (it) __syncthreads();
            issueV(kt); CPCOMMIT();
            if (it + 1 < ntiles) {
                issueK(kt+1, 1-cur); CPCOMMIT();
                CPWAIT(2);
            } else {
                CPWAIT(1);
            }
            __syncthreads();

            // ---- S = (Q/8) K^T ----
            float s[8][4];
            #pragma unroll
            for (int nt = 0; nt < 8; nt++)
                #pragma unroll
                for (int i = 0; i < 4; i++) s[nt][i] = 0.f;
            #pragma unroll
            for (int kc = 0; kc < 8; kc++) {
                int kb = kc*8;
                #pragma unroll
                for (int nt = 0; nt < 8; nt++) {
                    int col = nt*8 + g;
                    unsigned b0 = sK[cur][col*64 + SWK(col, kb+tig)];
                    unsigned b1 = sK[cur][col*64 + SWK(col, kb+tig+4)];
                    mma8(s[nt], qf[kc][0], qf[kc][1], qf[kc][2], qf[kc][3], b0, b1);
                }
            }

            // ---- mask + online softmax ----
            int c0 = kt*64;
            const float* am = amask + (size_t)b*(CL+QL) + c0;
            bool causal = (chunk == 1) && (it == ntiles-1);
            #pragma unroll
            for (int nt = 0; nt < 8; nt++) {
                int j0 = nt*8 + 2*tig, j1 = j0 + 1;
                float a0 = __ldg(am + j0), a1 = __ldg(am + j1);
                s[nt][0] += a0; s[nt][1] += a1; s[nt][2] += a0; s[nt][3] += a1;
                if (causal) {
                    int r0 = CL + qt*64 + m0 + g, r1 = r0 + 8;
                    int cj0 = c0 + j0, cj1 = c0 + j1;
                    if (cj0 > r0) s[nt][0] = -1e30f;
                    if (cj1 > r0) s[nt][1] = -1e30f;
                    if (cj0 > r1) s[nt][2] = -1e30f;
                    if (cj1 > r1) s[nt][3] = -1e30f;
                }
            }

            float mx0 = -1e30f, mx1 = -1e30f;
            #pragma unroll
            for (int nt = 0; nt < 8; nt++) {
                mx0 = fmaxf(mx0, fmaxf(s[nt][0], s[nt][1]));
                mx1 = fmaxf(mx1, fmaxf(s[nt][2], s[nt][3]));
            }
            mx0 = fmaxf(mx0, __shfl_xor_sync(0xffffffffu, mx0, 1));
            mx0 = fmaxf(mx0, __shfl_xor_sync(0xffffffffu, mx0, 2));
            mx1 = fmaxf(mx1, __shfl_xor_sync(0xffffffffu, mx1, 1));
            mx1 = fmaxf(mx1, __shfl_xor_sync(0xffffffffu, mx1, 2));

            float mn0 = fmaxf(mi0, mx0), mn1 = fmaxf(mi1, mx1);
            float cor0 = __expf(mi0 - mn0), cor1 = __expf(mi1 - mn1);
            mi0 = mn0; mi1 = mn1;

            float sum0 = 0.f, sum1 = 0.f;
            #pragma unroll
            for (int nt = 0; nt < 8; nt++) {
                s[nt][0] = __expf(s[nt][0] - mn0); sum0 += s[nt][0];
                s[nt][1] = __expf(s[nt][1] - mn0); sum0 += s[nt][1];
                s[nt][2] = __expf(s[nt][2] - mn1); sum1 += s[nt][2];
                s[nt][3] = __expf(s[nt][3] - mn1); sum1 += s[nt][3];
            }
            sum0 += __shfl_xor_sync(0xffffffffu, sum0, 1);
            sum0 += __shfl_xor_sync(0xffffffffu, sum0, 2);
            sum1 += __shfl_xor_sync(0xffffffffu, sum1, 1);
            sum1 += __shfl_xor_sync(0xffffffffu, sum1, 2);
            li0 = li0*cor0 + sum0;
            li1 = li1*cor1 + sum1;
            #pragma unroll
            for (int nt = 0; nt < 8; nt++) {
                O[nt][0] *= cor0; O[nt][1] *= cor0;
                O[nt][2] *= cor1; O[nt][3] *= cor1;
            }

            if (it + 1 < ntiles) { CPWAIT(1); } else { CPWAIT(0); }
            __syncthreads();

            // ---- O += P V  (P via cvt + shfl permutation) ----
            int l1 = (lane & 28) + (tig >> 1);
            int l2 = l1 + 2;
            bool odd = (tig & 1);
            #pragma unroll
            for (int kc = 0; kc < 8; kc++) {
                unsigned u0 = f2tf(s[kc][0]), u1 = f2tf(s[kc][1]);
                unsigned u2 = f2tf(s[kc][2]), u3 = f2tf(s[kc][3]);
                unsigned s00 = __shfl_sync(0xffffffffu, u0, l1);
                unsigned s01 = __shfl_sync(0xffffffffu, u1, l1);
                unsigned s02 = __shfl_sync(0xffffffffu, u2, l1);
                unsigned s03 = __shfl_sync(0xffffffffu, u3, l1);
                unsigned s10 = __shfl_sync(0xffffffffu, u0, l2);
                unsigned s11 = __shfl_sync(0xffffffffu, u1, l2);
                unsigned s12 = __shfl_sync(0xffffffffu, u2, l2);
                unsigned s13 = __shfl_sync(0xffffffffu, u3, l2);
                unsigned a0 = odd ? s01 : s00;
                unsigned a1 = odd ? s03 : s02;
                unsigned a2 = odd ? s11 : s10;
                unsigned a3 = odd ? s13 : s12;
                int kb = kc*8;
                #pragma unroll
                for (int nt = 0; nt < 8; nt++) {
                    int dcol = nt*8 + g;
                    unsigned b0 = sV[(kb+tig  )*64 + SWV(kb+tig,   dcol)];
                    unsigned b1 = sV[(kb+tig+4)*64 + SWV(kb+tig+4, dcol)];
                    mma8(O[nt], a0, a1, a2, a3, b0, b1);
                }
            }
        }

        // ---- write partials (unnormalized O, m, l) ----
        size_t rowbase = ((size_t)(b*NH + h))*QL + qt*64;
        float* po = g_po + ((size_t)chunk*PO_ROWS + rowbase)*HD;
        #pragma unroll
        for (int nt = 0; nt < 8; nt++) {
            int col = nt*8 + 2*tig;
            *(float2*)&po[(size_t)(m0+g)*HD + col]   = make_float2(O[nt][0], O[nt][1]);
            *(float2*)&po[(size_t)(m0+g+8)*HD + col] = make_float2(O[nt][2], O[nt][3]);
        }
        if (tig == 0) {
            size_t mb = (size_t)chunk*PO_ROWS + rowbase;
            g_pm[mb + m0 + g]     = mi0;
            g_pl[mb + m0 + g]     = li0;
            g_pm[mb + m0 + g + 8] = mi1;
            g_pl[mb + m0 + g + 8] = li1;
        }
    }
}

// ---------------- combine split-KV partials -> ctx (tf32) --------------------
__global__ void combine_attn()
{
    int idx = blockIdx.x*256 + threadIdx.x;      // 0 .. 524287
    int d4  = idx & 15;
    int row = idx >> 4;                          // 0 .. 32767

    float m0 = g_pm[row], m1 = g_pm[PO_ROWS + row];
    float l0 = g_pl[row], l1 = g_pl[PO_ROWS + row];
    float m  = fmaxf(m0, m1);
    float w0 = __expf(m0 - m), w1 = __expf(m1 - m);
    float inv = 1.f / (w0*l0 + w1*l1);
    w0 *= inv; w1 *= inv;

    float4 o0 = ((const float4*)g_po)[(size_t)row*16 + d4];
    float4 o1 = ((const float4*)g_po)[(size_t)(PO_ROWS + row)*16 + d4];

    uint4 u;
    u.x = f2tf(w0*o0.x + w1*o1.x);
    u.y = f2tf(w0*o0.y + w1*o1.y);
    u.z = f2tf(w0*o0.z + w1*o1.z);
    u.w = f2tf(w0*o0.w + w1*o1.w);

    int q = row & 511, h = (row >> 9) & 15, b = row >> 13;
    ((uint4*)g_ctx)[(size_t)(b*QL + q)*(E/4) + h*(HD/4) + d4] = u;
}

// ---------------- launch ----------------------------------------------------
extern "C" void kernel_launch(void* const* d_in, const int* in_sizes, int n_in,
                              void* d_out, int out_size)
{
    const float* X     = (const float*)d_in[0];
    const float* amask = (const float*)d_in[1];
    const float* kc    = (const float*)d_in[2];
    const float* vc    = (const float*)d_in[3];
    const float* Wq    = (const float*)d_in[4];
    const float* bq    = (const float*)d_in[5];
    const float* Wk    = (const float*)d_in[6];
    const float* bk    = (const float*)d_in[7];
    const float* Wv    = (const float*)d_in[8];
    const float* bv    = (const float*)d_in[9];
    const float* Wo    = (const float*)d_in[10];
    const float* bo    = (const float*)d_in[11];
    float* out = (float*)d_out;

    init_work<<<1, 1>>>();
    convert_tf32<<<6144, 256>>>((const float4*)X, (const float4*)Wq,
                                (const float4*)Wk, (const float4*)Wv,
                                (const float4*)Wo);
    {
        int total = BZ*CL*E/4;
        copy_cache<<<(total + 255)/256, 256>>>((const float4*)kc,
                                               (const float4*)vc, out);
    }
    {
        dim3 grid(3*E/128, MROWS/128);       // 24 x 16
        gemm_qkv<<<grid, 256>>>(bq, bk, bv, out);
    }
    attn<<<ATTN_BLOCKS, 128>>>(amask);
    combine_attn<<<2048, 256>>>();
    {
        dim3 grid(E/128, MROWS/128);         // 8 x 16
        gemm_out<<<grid, 256>>>(bo, out);
    }
}